// round 1
// baseline (speedup 1.0000x reference)
#include <cuda_runtime.h>
#include <math.h>

// ---------------- problem constants ----------------
#define S_    4
#define N_    10000
#define L_    8
#define F_    128      // F_IN == H
#define G3_   384      // 3*H
#define OR_   64       // ORIG
#define SUB_  100
#define SEQ_  (S_*N_)  // 40000
#define MB_   64       // sequences per block in GRU kernels
#define NT_   256      // threads per block in GEMM-style kernels
#define NB_LOSS (S_*SUB_*(L_-1))  // 2800
#define LOSS_CNT 179200.0f        // S*SUB*(L-1)*ORIG

// ---------------- device scratch (static, no allocations) ----------------
__device__ int      g_walksf[SEQ_*L_];        // flipped walks, [seq][t]
__device__ unsigned g_upk[SEQ_];              // packed flipped uniq (4 bits per t)
__device__ float    g_wg[8*G3_];              // GRU1 gi table: Wih_w[:,u]+bih_w
__device__ float    g_P[N_*G3_];              // h @ WihA^T + bih  (15 MB)
__device__ float    g_ywalk[L_][SEQ_*F_];     // GRU1 outputs (164 MB)
__device__ float    g_yseq[L_-1][SEQ_*F_];    // GRU2 outputs t=0..6 (143 MB)
__device__ float    g_part1[NB_LOSS];
__device__ float    g_part2[NB_LOSS];
__device__ float    g_posw;

// ---------------- helpers ----------------
__device__ __forceinline__ float sigf(float x) {
    return __fdividef(1.f, 1.f + __expf(-x));
}
__device__ __forceinline__ float tanh_s(float x) {
    float ax = fabsf(x);
    float e  = __expf(-2.f * ax);
    float r  = __fdividef(1.f - e, 1.f + e);
    return copysignf(r, x);
}
__device__ __forceinline__ float softplusf(float x) {
    return fmaxf(x, 0.f) + log1pf(__expf(-fabsf(x)));
}

// Tiled GEMM chunk: acc[4][8] += sh_src(64x128, row stride 132) @ W^T
// W: base pointer for j=0 of this 128-col group, row stride wstride.
// Thread (tx,ty): rows m = ty*4+{0..3}, cols j = tx*8+{0..7}.
// Contains __syncthreads() — must be called from uniform control flow.
__device__ __forceinline__ void gemm_tile(float acc[4][8],
                                          const float* __restrict__ sh_src,
                                          float* __restrict__ sh_w,
                                          const float* __restrict__ W,
                                          int wstride, int tx, int ty, int tid)
{
    for (int k0 = 0; k0 < F_; k0 += 32) {
        __syncthreads();   // protect sh_w from previous use
        {
            int j = tid >> 1, half = tid & 1;
            const float* src = W + (size_t)j * wstride + k0 + half * 16;
#pragma unroll
            for (int q = 0; q < 4; q++) {
                float4 v = *(const float4*)(src + q * 4);
                int kk = half * 16 + q * 4;
                sh_w[(kk+0)*128 + j] = v.x;
                sh_w[(kk+1)*128 + j] = v.y;
                sh_w[(kk+2)*128 + j] = v.z;
                sh_w[(kk+3)*128 + j] = v.w;
            }
        }
        __syncthreads();
        const float* s0 = sh_src + (ty*4+0)*132 + k0;
        const float* s1 = sh_src + (ty*4+1)*132 + k0;
        const float* s2 = sh_src + (ty*4+2)*132 + k0;
        const float* s3 = sh_src + (ty*4+3)*132 + k0;
#pragma unroll 8
        for (int kk = 0; kk < 32; kk++) {
            float4 wa = *(const float4*)&sh_w[kk*128 + tx*8];
            float4 wb = *(const float4*)&sh_w[kk*128 + tx*8 + 4];
            float h0 = s0[kk], h1 = s1[kk], h2 = s2[kk], h3 = s3[kk];
            acc[0][0]+=h0*wa.x; acc[0][1]+=h0*wa.y; acc[0][2]+=h0*wa.z; acc[0][3]+=h0*wa.w;
            acc[0][4]+=h0*wb.x; acc[0][5]+=h0*wb.y; acc[0][6]+=h0*wb.z; acc[0][7]+=h0*wb.w;
            acc[1][0]+=h1*wa.x; acc[1][1]+=h1*wa.y; acc[1][2]+=h1*wa.z; acc[1][3]+=h1*wa.w;
            acc[1][4]+=h1*wb.x; acc[1][5]+=h1*wb.y; acc[1][6]+=h1*wb.z; acc[1][7]+=h1*wb.w;
            acc[2][0]+=h2*wa.x; acc[2][1]+=h2*wa.y; acc[2][2]+=h2*wa.z; acc[2][3]+=h2*wa.w;
            acc[2][4]+=h2*wb.x; acc[2][5]+=h2*wb.y; acc[2][6]+=h2*wb.z; acc[2][7]+=h2*wb.w;
            acc[3][0]+=h3*wa.x; acc[3][1]+=h3*wa.y; acc[3][2]+=h3*wa.z; acc[3][3]+=h3*wa.w;
            acc[3][4]+=h3*wb.x; acc[3][5]+=h3*wb.y; acc[3][6]+=h3*wb.z; acc[3][7]+=h3*wb.w;
        }
    }
}

// ---------------- preprocessing ----------------
__global__ void prep_kernel(const int* __restrict__ walks)
{
    int m = blockIdx.x * blockDim.x + threadIdx.x;
    if (m >= SEQ_) return;
    int w[L_];
#pragma unroll
    for (int p = 0; p < L_; p++) w[p] = walks[m*L_ + p];
    unsigned pk = 0;
#pragma unroll
    for (int t = 0; t < L_; t++) {
        int p = L_-1-t;
        int wp = w[p];
        int u = p;
#pragma unroll
        for (int q = L_-1; q >= 0; q--) if (w[q] == wp) u = q;   // first occurrence
        g_walksf[m*L_ + t] = wp;
        pk |= ((unsigned)u) << (4*t);
    }
    g_upk[m] = pk;
}

__global__ void wg_kernel(const float* __restrict__ Wih_w,
                          const float* __restrict__ bih_w)
{
    int j = threadIdx.x;   // 384
    float b = bih_w[j];
#pragma unroll
    for (int u = 0; u < 8; u++) g_wg[u*G3_ + j] = Wih_w[j*8 + u] + b;
}

// P = h @ WihA^T + bih  (WihA = Wih[:, 0:128])
__global__ void __launch_bounds__(NT_) p_kernel(const float* __restrict__ h,
                                                const float* __restrict__ Wih,
                                                const float* __restrict__ bih)
{
    extern __shared__ float sm[];
    float* sh_s = sm;                  // 64*132
    float* sh_w = sh_s + MB_*132;      // 32*128
    int tid = threadIdx.x, tx = tid & 15, ty = tid >> 4;
    int r0 = blockIdx.x * MB_;

    for (int i = tid; i < MB_*F_; i += NT_) {
        int r = i >> 7, k = i & 127;
        int n = r0 + r;
        sh_s[r*132 + k] = (n < N_) ? h[(size_t)n*F_ + k] : 0.f;
    }
    __syncthreads();

    for (int jg = 0; jg < 3; jg++) {
        int jbase = jg*F_ + tx*8;
        float acc[4][8];
        {
            const float4* bp = (const float4*)(bih + jbase);
            float4 a = bp[0], b = bp[1];
            float bb[8] = {a.x,a.y,a.z,a.w,b.x,b.y,b.z,b.w};
#pragma unroll
            for (int mm = 0; mm < 4; mm++)
#pragma unroll
                for (int jj = 0; jj < 8; jj++) acc[mm][jj] = bb[jj];
        }
        gemm_tile(acc, sh_s, sh_w, Wih + (size_t)jg*F_*256, 256, tx, ty, tid);
#pragma unroll
        for (int mm = 0; mm < 4; mm++) {
            int n = r0 + ty*4 + mm;
            if (n < N_) {
                float4 v0 = make_float4(acc[mm][0],acc[mm][1],acc[mm][2],acc[mm][3]);
                float4 v1 = make_float4(acc[mm][4],acc[mm][5],acc[mm][6],acc[mm][7]);
                *(float4*)(g_P + (size_t)n*G3_ + jbase)     = v0;
                *(float4*)(g_P + (size_t)n*G3_ + jbase + 4) = v1;
            }
        }
    }
}

// ---------------- fused GRU (all 8 steps inside one kernel) ----------------
// IS2==0: GRU1 (gi = table lookup, h0 = 0, writes g_ywalk[t])
// IS2==1: GRU2 (gi = P gather + x@WihB^T, h0 = g_ywalk[7], writes g_yseq / hT)
template<int IS2>
__global__ void __launch_bounds__(NT_) gru_kernel(const float* __restrict__ Whh,
                                                  const float* __restrict__ bhh,
                                                  const float* __restrict__ Wih,
                                                  float* __restrict__ hT_out)
{
    extern __shared__ float sm[];
    float* sh_h = sm;                       // 64*132
    float* sh_b = sh_h + MB_*132;           // 64*132 (x for GRU2) or wg table (GRU1)
    float* sh_w = sh_b + MB_*132;           // 32*128
    int*   sh_i = (int*)(sh_w + 32*128);    // 64 ints (upk / node)

    const int tid = threadIdx.x, tx = tid & 15, ty = tid >> 4;
    const int m0 = blockIdx.x * MB_;

    if constexpr (IS2) {
        for (int i = tid; i < MB_*F_; i += NT_) {
            int r = i >> 7, k = i & 127;
            sh_h[r*132 + k] = g_ywalk[L_-1][(size_t)(m0+r)*F_ + k];
        }
    } else {
        for (int i = tid; i < MB_*132; i += NT_) sh_h[i] = 0.f;
        for (int i = tid; i < 8*G3_;   i += NT_) sh_b[i] = g_wg[i];
        if (tid < MB_) sh_i[tid] = (int)g_upk[m0 + tid];
    }
    __syncthreads();

    for (int t = 0; t < L_; t++) {
        if constexpr (IS2) {
            for (int i = tid; i < MB_*F_; i += NT_) {
                int r = i >> 7, k = i & 127;
                sh_b[r*132 + k] = g_ywalk[t][(size_t)(m0+r)*F_ + k];
            }
            if (tid < MB_) sh_i[tid] = g_walksf[(size_t)(m0+tid)*L_ + t];
            __syncthreads();
        }

        float rr[4][8], zz[4][8];

        for (int jg = 0; jg < 3; jg++) {
            const int jbase = jg*F_ + tx*8;
            float ai[4][8], ah[4][8];

            // gi init (bias included via P / wg table)
#pragma unroll
            for (int mm = 0; mm < 4; mm++) {
                const int m = ty*4 + mm;
                const float4* p;
                if constexpr (IS2) {
                    p = (const float4*)(g_P + (size_t)sh_i[m]*G3_ + jbase);
                } else {
                    const int u = (sh_i[m] >> (4*t)) & 7;
                    p = (const float4*)(sh_b + u*G3_ + jbase);
                }
                float4 a = p[0], b = p[1];
                ai[mm][0]=a.x; ai[mm][1]=a.y; ai[mm][2]=a.z; ai[mm][3]=a.w;
                ai[mm][4]=b.x; ai[mm][5]=b.y; ai[mm][6]=b.z; ai[mm][7]=b.w;
            }
            if constexpr (IS2) {
                // gi += x @ WihB^T   (WihB = Wih[:, 128:256])
                gemm_tile(ai, sh_b, sh_w, Wih + (size_t)jg*F_*256 + F_, 256, tx, ty, tid);
            }

            // gh init with bhh
            {
                const float4* bp = (const float4*)(bhh + jbase);
                float4 a = bp[0], b = bp[1];
                float bb[8] = {a.x,a.y,a.z,a.w,b.x,b.y,b.z,b.w};
#pragma unroll
                for (int mm = 0; mm < 4; mm++)
#pragma unroll
                    for (int jj = 0; jj < 8; jj++) ah[mm][jj] = bb[jj];
            }
            gemm_tile(ah, sh_h, sh_w, Whh + (size_t)jg*F_*F_, F_, tx, ty, tid);

            if (jg == 0) {
#pragma unroll
                for (int mm = 0; mm < 4; mm++)
#pragma unroll
                    for (int jj = 0; jj < 8; jj++)
                        rr[mm][jj] = sigf(ai[mm][jj] + ah[mm][jj]);
            } else if (jg == 1) {
#pragma unroll
                for (int mm = 0; mm < 4; mm++)
#pragma unroll
                    for (int jj = 0; jj < 8; jj++)
                        zz[mm][jj] = sigf(ai[mm][jj] + ah[mm][jj]);
            } else {
                __syncthreads();   // everyone done reading sh_h for GEMMs
#pragma unroll
                for (int mm = 0; mm < 4; mm++) {
                    const int m = ty*4 + mm;
#pragma unroll
                    for (int jj = 0; jj < 8; jj++) {
                        float nv = tanh_s(ai[mm][jj] + rr[mm][jj]*ah[mm][jj]);
                        float ho = sh_h[m*132 + tx*8 + jj];
                        sh_h[m*132 + tx*8 + jj] = (1.f - zz[mm][jj])*nv + zz[mm][jj]*ho;
                    }
                }
            }
        }
        __syncthreads();

        // dump step output
        if constexpr (IS2) {
            float* dst = (t < L_-1) ? g_yseq[t] : hT_out;
            for (int i = tid; i < MB_*F_; i += NT_) {
                int r = i >> 7, k = i & 127;
                dst[(size_t)(m0+r)*F_ + k] = sh_h[r*132 + k];
            }
        } else {
            for (int i = tid; i < MB_*F_; i += NT_) {
                int r = i >> 7, k = i & 127;
                g_ywalk[t][(size_t)(m0+r)*F_ + k] = sh_h[r*132 + k];
            }
        }
        __syncthreads();
    }
}

// ---------------- loss ----------------
__global__ void lsum_kernel(const int* __restrict__ idxs, const float* __restrict__ y0)
{
    int b = blockIdx.x;
    int t = b % (L_-1), j = (b/(L_-1)) % SUB_, s = b/((L_-1)*SUB_);
    int seq  = s*N_ + idxs[j];
    int node = g_walksf[(size_t)seq*L_ + t + 1];
    int o = threadIdx.x;   // 64
    float v = y0[(size_t)node*OR_ + o];
    __shared__ float red[OR_];
    red[o] = v; __syncthreads();
    for (int st = OR_/2; st > 0; st >>= 1) {
        if (o < st) red[o] += red[o+st];
        __syncthreads();
    }
    if (o == 0) g_part1[b] = red[0];
}

__global__ void lred1_kernel()
{
    __shared__ float red[256];
    int tid = threadIdx.x;
    float s = 0.f;
    for (int i = tid; i < NB_LOSS; i += 256) s += g_part1[i];
    red[tid] = s; __syncthreads();
    for (int st = 128; st > 0; st >>= 1) {
        if (tid < st) red[tid] += red[tid+st];
        __syncthreads();
    }
    if (tid == 0) g_posw = LOSS_CNT / red[0];
}

__global__ void lbce_kernel(const int* __restrict__ idxs, const float* __restrict__ y0,
                            const float* __restrict__ Wss, const float* __restrict__ bss)
{
    int b = blockIdx.x;
    int t = b % (L_-1), j = (b/(L_-1)) % SUB_, s = b/((L_-1)*SUB_);
    int seq = s*N_ + idxs[j];
    __shared__ float yrow[F_];
    int o = threadIdx.x;   // 64
    yrow[o]      = g_yseq[t][(size_t)seq*F_ + o];
    yrow[o + 64] = g_yseq[t][(size_t)seq*F_ + o + 64];
    __syncthreads();
    float acc = bss[o];
    const float4* wr = (const float4*)(Wss + (size_t)o*F_);
#pragma unroll 8
    for (int k = 0; k < F_/4; k++) {
        float4 w = wr[k];
        acc += yrow[k*4+0]*w.x + yrow[k*4+1]*w.y + yrow[k*4+2]*w.z + yrow[k*4+3]*w.w;
    }
    int node = g_walksf[(size_t)seq*L_ + t + 1];
    float yt = y0[(size_t)node*OR_ + o];
    float term = g_posw * yt * softplusf(-acc) + (1.f - yt) * softplusf(acc);
    __shared__ float red[OR_];
    red[o] = term; __syncthreads();
    for (int st = OR_/2; st > 0; st >>= 1) {
        if (o < st) red[o] += red[o+st];
        __syncthreads();
    }
    if (o == 0) g_part2[b] = red[0];
}

__global__ void lred2_kernel(float* __restrict__ dst)
{
    __shared__ float red[256];
    int tid = threadIdx.x;
    float s = 0.f;
    for (int i = tid; i < NB_LOSS; i += 256) s += g_part2[i];
    red[tid] = s; __syncthreads();
    for (int st = 128; st > 0; st >>= 1) {
        if (tid < st) red[tid] += red[tid+st];
        __syncthreads();
    }
    if (tid == 0) *dst = red[0] / LOSS_CNT;
}

// ---------------- launch ----------------
extern "C" void kernel_launch(void* const* d_in, const int* in_sizes, int n_in,
                              void* d_out, int out_size)
{
    const float* h     = (const float*)d_in[0];
    const float* y0    = (const float*)d_in[1];
    const float* Wih_w = (const float*)d_in[2];
    const float* Whh_w = (const float*)d_in[3];
    const float* bih_w = (const float*)d_in[4];
    const float* bhh_w = (const float*)d_in[5];
    const float* Wih   = (const float*)d_in[6];
    const float* Whh   = (const float*)d_in[7];
    const float* bih   = (const float*)d_in[8];
    const float* bhh   = (const float*)d_in[9];
    const float* W_ss  = (const float*)d_in[10];
    const float* b_ss  = (const float*)d_in[11];
    const int*   walks = (const int*)d_in[12];
    const int*   idxs  = (const int*)d_in[13];
    float* out = (float*)d_out;

    const int SMEM_GRU = (MB_*132*2 + 32*128) * 4 + MB_ * 4;   // 84224 B
    const int SMEM_P   = (MB_*132 + 32*128) * 4;               // 50176 B
    cudaFuncSetAttribute(gru_kernel<0>, cudaFuncAttributeMaxDynamicSharedMemorySize, SMEM_GRU);
    cudaFuncSetAttribute(gru_kernel<1>, cudaFuncAttributeMaxDynamicSharedMemorySize, SMEM_GRU);
    cudaFuncSetAttribute(p_kernel,      cudaFuncAttributeMaxDynamicSharedMemorySize, SMEM_P);

    prep_kernel<<<(SEQ_ + 255)/256, 256>>>(walks);
    wg_kernel<<<1, G3_>>>(Wih_w, bih_w);
    p_kernel<<<(N_ + MB_-1)/MB_, NT_, SMEM_P>>>(h, Wih, bih);
    gru_kernel<0><<<SEQ_/MB_, NT_, SMEM_GRU>>>(Whh_w, bhh_w, nullptr, nullptr);
    gru_kernel<1><<<SEQ_/MB_, NT_, SMEM_GRU>>>(Whh, bhh, Wih, out);
    lsum_kernel<<<NB_LOSS, OR_>>>(idxs, y0);
    lred1_kernel<<<1, 256>>>();
    lbce_kernel<<<NB_LOSS, OR_>>>(idxs, y0, W_ss, b_ss);
    lred2_kernel<<<1, 256>>>(out + (out_size - 1));
}

// round 2
// speedup vs baseline: 1.0014x; 1.0014x over previous
#include <cuda_runtime.h>
#include <math.h>

// ---------------- problem constants ----------------
#define S_    4
#define N_    10000
#define L_    8
#define F_    128      // F_IN == H
#define G3_   384      // 3*H
#define OR_   64       // ORIG
#define SUB_  100
#define SEQ_  (S_*N_)  // 40000
#define MB_   64       // sequences per block in GRU kernels
#define NT_   256      // threads per block in GEMM-style kernels
#define NB_LOSS (S_*SUB_*(L_-1))  // 2800
#define LOSS_CNT 179200.0f        // S*SUB*(L-1)*ORIG

// ---------------- device scratch (static, no allocations) ----------------
__device__ int      g_walksf[SEQ_*L_];        // flipped walks, [seq][t]
__device__ unsigned g_upk[SEQ_];              // packed flipped uniq (4 bits per t)
__device__ float    g_wg[8*G3_];              // GRU1 gi table: Wih_w[:,u]+bih_w
__device__ float    g_P[N_*G3_];              // h @ WihA^T + bih  (15 MB)
__device__ float    g_ywalk[L_][SEQ_*F_];     // GRU1 outputs (164 MB)
__device__ float    g_yseq[L_-1][SEQ_*F_];    // GRU2 outputs t=0..6 (143 MB)
__device__ float    g_part1[NB_LOSS];
__device__ float    g_part2[NB_LOSS];
__device__ float    g_posw;

// ---------------- helpers ----------------
__device__ __forceinline__ float sigf(float x) {
    return __fdividef(1.f, 1.f + __expf(-x));
}
__device__ __forceinline__ float tanh_s(float x) {
    float ax = fabsf(x);
    float e  = __expf(-2.f * ax);
    float r  = __fdividef(1.f - e, 1.f + e);
    return copysignf(r, x);
}
__device__ __forceinline__ float softplusf(float x) {
    return fmaxf(x, 0.f) + log1pf(__expf(-fabsf(x)));
}

// Tiled GEMM chunk: acc[4][8] += sh_src(64x128, row stride 132) @ W^T
// W: base pointer for j=0 of this 128-col group, row stride wstride.
// Thread (tx,ty): rows m = ty*4+{0..3}, cols j = tx*8+{0..7}.
// Contains __syncthreads() — must be called from uniform control flow.
__device__ __forceinline__ void gemm_tile(float acc[4][8],
                                          const float* __restrict__ sh_src,
                                          float* __restrict__ sh_w,
                                          const float* __restrict__ W,
                                          int wstride, int tx, int ty, int tid)
{
    for (int k0 = 0; k0 < F_; k0 += 32) {
        __syncthreads();   // protect sh_w from previous use
        {
            int j = tid >> 1, half = tid & 1;
            const float* src = W + (size_t)j * wstride + k0 + half * 16;
#pragma unroll
            for (int q = 0; q < 4; q++) {
                float4 v = *(const float4*)(src + q * 4);
                int kk = half * 16 + q * 4;
                sh_w[(kk+0)*128 + j] = v.x;
                sh_w[(kk+1)*128 + j] = v.y;
                sh_w[(kk+2)*128 + j] = v.z;
                sh_w[(kk+3)*128 + j] = v.w;
            }
        }
        __syncthreads();
        const float* s0 = sh_src + (ty*4+0)*132 + k0;
        const float* s1 = sh_src + (ty*4+1)*132 + k0;
        const float* s2 = sh_src + (ty*4+2)*132 + k0;
        const float* s3 = sh_src + (ty*4+3)*132 + k0;
#pragma unroll 8
        for (int kk = 0; kk < 32; kk++) {
            float4 wa = *(const float4*)&sh_w[kk*128 + tx*8];
            float4 wb = *(const float4*)&sh_w[kk*128 + tx*8 + 4];
            float h0 = s0[kk], h1 = s1[kk], h2 = s2[kk], h3 = s3[kk];
            acc[0][0]+=h0*wa.x; acc[0][1]+=h0*wa.y; acc[0][2]+=h0*wa.z; acc[0][3]+=h0*wa.w;
            acc[0][4]+=h0*wb.x; acc[0][5]+=h0*wb.y; acc[0][6]+=h0*wb.z; acc[0][7]+=h0*wb.w;
            acc[1][0]+=h1*wa.x; acc[1][1]+=h1*wa.y; acc[1][2]+=h1*wa.z; acc[1][3]+=h1*wa.w;
            acc[1][4]+=h1*wb.x; acc[1][5]+=h1*wb.y; acc[1][6]+=h1*wb.z; acc[1][7]+=h1*wb.w;
            acc[2][0]+=h2*wa.x; acc[2][1]+=h2*wa.y; acc[2][2]+=h2*wa.z; acc[2][3]+=h2*wa.w;
            acc[2][4]+=h2*wb.x; acc[2][5]+=h2*wb.y; acc[2][6]+=h2*wb.z; acc[2][7]+=h2*wb.w;
            acc[3][0]+=h3*wa.x; acc[3][1]+=h3*wa.y; acc[3][2]+=h3*wa.z; acc[3][3]+=h3*wa.w;
            acc[3][4]+=h3*wb.x; acc[3][5]+=h3*wb.y; acc[3][6]+=h3*wb.z; acc[3][7]+=h3*wb.w;
        }
    }
}

// ---------------- preprocessing ----------------
__global__ void prep_kernel(const int* __restrict__ walks)
{
    int m = blockIdx.x * blockDim.x + threadIdx.x;
    if (m >= SEQ_) return;
    int w[L_];
#pragma unroll
    for (int p = 0; p < L_; p++) w[p] = walks[m*L_ + p];
    unsigned pk = 0;
#pragma unroll
    for (int t = 0; t < L_; t++) {
        int p = L_-1-t;
        int wp = w[p];
        int u = p;
#pragma unroll
        for (int q = L_-1; q >= 0; q--) if (w[q] == wp) u = q;   // first occurrence
        g_walksf[m*L_ + t] = wp;
        pk |= ((unsigned)u) << (4*t);
    }
    g_upk[m] = pk;
}

__global__ void wg_kernel(const float* __restrict__ Wih_w,
                          const float* __restrict__ bih_w)
{
    int j = threadIdx.x;   // 384
    float b = bih_w[j];
#pragma unroll
    for (int u = 0; u < 8; u++) g_wg[u*G3_ + j] = Wih_w[j*8 + u] + b;
}

// P = h @ WihA^T + bih  (WihA = Wih[:, 0:128])
__global__ void __launch_bounds__(NT_) p_kernel(const float* __restrict__ h,
                                                const float* __restrict__ Wih,
                                                const float* __restrict__ bih)
{
    extern __shared__ float sm[];
    float* sh_s = sm;                  // 64*132
    float* sh_w = sh_s + MB_*132;      // 32*128
    int tid = threadIdx.x, tx = tid & 15, ty = tid >> 4;
    int r0 = blockIdx.x * MB_;

    for (int i = tid; i < MB_*F_; i += NT_) {
        int r = i >> 7, k = i & 127;
        int n = r0 + r;
        sh_s[r*132 + k] = (n < N_) ? h[(size_t)n*F_ + k] : 0.f;
    }
    __syncthreads();

    for (int jg = 0; jg < 3; jg++) {
        int jbase = jg*F_ + tx*8;
        float acc[4][8];
        {
            const float4* bp = (const float4*)(bih + jbase);
            float4 a = bp[0], b = bp[1];
            float bb[8] = {a.x,a.y,a.z,a.w,b.x,b.y,b.z,b.w};
#pragma unroll
            for (int mm = 0; mm < 4; mm++)
#pragma unroll
                for (int jj = 0; jj < 8; jj++) acc[mm][jj] = bb[jj];
        }
        gemm_tile(acc, sh_s, sh_w, Wih + (size_t)jg*F_*256, 256, tx, ty, tid);
#pragma unroll
        for (int mm = 0; mm < 4; mm++) {
            int n = r0 + ty*4 + mm;
            if (n < N_) {
                float4 v0 = make_float4(acc[mm][0],acc[mm][1],acc[mm][2],acc[mm][3]);
                float4 v1 = make_float4(acc[mm][4],acc[mm][5],acc[mm][6],acc[mm][7]);
                *(float4*)(g_P + (size_t)n*G3_ + jbase)     = v0;
                *(float4*)(g_P + (size_t)n*G3_ + jbase + 4) = v1;
            }
        }
    }
}

// ---------------- fused GRU (all 8 steps inside one kernel) ----------------
// IS2==0: GRU1 (gi = table lookup, h0 = 0, writes g_ywalk[t])
// IS2==1: GRU2 (gi = P gather + x@WihB^T, h0 = g_ywalk[7], writes g_yseq / hT)
template<int IS2>
__global__ void __launch_bounds__(NT_) gru_kernel(const float* __restrict__ Whh,
                                                  const float* __restrict__ bhh,
                                                  const float* __restrict__ Wih,
                                                  float* __restrict__ hT_out)
{
    extern __shared__ float sm[];
    float* sh_h = sm;                       // 64*132
    float* sh_b = sh_h + MB_*132;           // 64*132 (x for GRU2) or wg table (GRU1)
    float* sh_w = sh_b + MB_*132;           // 32*128
    int*   sh_i = (int*)(sh_w + 32*128);    // 64 ints (upk / node)

    const int tid = threadIdx.x, tx = tid & 15, ty = tid >> 4;
    const int m0 = blockIdx.x * MB_;

    if constexpr (IS2) {
        for (int i = tid; i < MB_*F_; i += NT_) {
            int r = i >> 7, k = i & 127;
            sh_h[r*132 + k] = g_ywalk[L_-1][(size_t)(m0+r)*F_ + k];
        }
    } else {
        for (int i = tid; i < MB_*132; i += NT_) sh_h[i] = 0.f;
        for (int i = tid; i < 8*G3_;   i += NT_) sh_b[i] = g_wg[i];
        if (tid < MB_) sh_i[tid] = (int)g_upk[m0 + tid];
    }
    __syncthreads();

    for (int t = 0; t < L_; t++) {
        if constexpr (IS2) {
            for (int i = tid; i < MB_*F_; i += NT_) {
                int r = i >> 7, k = i & 127;
                sh_b[r*132 + k] = g_ywalk[t][(size_t)(m0+r)*F_ + k];
            }
            if (tid < MB_) sh_i[tid] = g_walksf[(size_t)(m0+tid)*L_ + t];
            __syncthreads();
        }

        float rr[4][8], zz[4][8];

        for (int jg = 0; jg < 3; jg++) {
            const int jbase = jg*F_ + tx*8;
            float ai[4][8], ah[4][8];

            // gi init (bias included via P / wg table)
#pragma unroll
            for (int mm = 0; mm < 4; mm++) {
                const int m = ty*4 + mm;
                const float4* p;
                if constexpr (IS2) {
                    p = (const float4*)(g_P + (size_t)sh_i[m]*G3_ + jbase);
                } else {
                    const int u = (sh_i[m] >> (4*t)) & 7;
                    p = (const float4*)(sh_b + u*G3_ + jbase);
                }
                float4 a = p[0], b = p[1];
                ai[mm][0]=a.x; ai[mm][1]=a.y; ai[mm][2]=a.z; ai[mm][3]=a.w;
                ai[mm][4]=b.x; ai[mm][5]=b.y; ai[mm][6]=b.z; ai[mm][7]=b.w;
            }
            if constexpr (IS2) {
                // gi += x @ WihB^T   (WihB = Wih[:, 128:256])
                gemm_tile(ai, sh_b, sh_w, Wih + (size_t)jg*F_*256 + F_, 256, tx, ty, tid);
            }

            // gh init with bhh
            {
                const float4* bp = (const float4*)(bhh + jbase);
                float4 a = bp[0], b = bp[1];
                float bb[8] = {a.x,a.y,a.z,a.w,b.x,b.y,b.z,b.w};
#pragma unroll
                for (int mm = 0; mm < 4; mm++)
#pragma unroll
                    for (int jj = 0; jj < 8; jj++) ah[mm][jj] = bb[jj];
            }
            gemm_tile(ah, sh_h, sh_w, Whh + (size_t)jg*F_*F_, F_, tx, ty, tid);

            if (jg == 0) {
#pragma unroll
                for (int mm = 0; mm < 4; mm++)
#pragma unroll
                    for (int jj = 0; jj < 8; jj++)
                        rr[mm][jj] = sigf(ai[mm][jj] + ah[mm][jj]);
            } else if (jg == 1) {
#pragma unroll
                for (int mm = 0; mm < 4; mm++)
#pragma unroll
                    for (int jj = 0; jj < 8; jj++)
                        zz[mm][jj] = sigf(ai[mm][jj] + ah[mm][jj]);
            } else {
                __syncthreads();   // everyone done reading sh_h for GEMMs
#pragma unroll
                for (int mm = 0; mm < 4; mm++) {
                    const int m = ty*4 + mm;
#pragma unroll
                    for (int jj = 0; jj < 8; jj++) {
                        float nv = tanh_s(ai[mm][jj] + rr[mm][jj]*ah[mm][jj]);
                        float ho = sh_h[m*132 + tx*8 + jj];
                        sh_h[m*132 + tx*8 + jj] = (1.f - zz[mm][jj])*nv + zz[mm][jj]*ho;
                    }
                }
            }
        }
        __syncthreads();

        // dump step output
        if constexpr (IS2) {
            float* dst = (t < L_-1) ? g_yseq[t] : hT_out;
            for (int i = tid; i < MB_*F_; i += NT_) {
                int r = i >> 7, k = i & 127;
                dst[(size_t)(m0+r)*F_ + k] = sh_h[r*132 + k];
            }
        } else {
            for (int i = tid; i < MB_*F_; i += NT_) {
                int r = i >> 7, k = i & 127;
                g_ywalk[t][(size_t)(m0+r)*F_ + k] = sh_h[r*132 + k];
            }
        }
        __syncthreads();
    }
}

// ---------------- loss ----------------
__global__ void lsum_kernel(const int* __restrict__ idxs, const float* __restrict__ y0)
{
    int b = blockIdx.x;
    int t = b % (L_-1), j = (b/(L_-1)) % SUB_, s = b/((L_-1)*SUB_);
    int seq  = s*N_ + idxs[j];
    int node = g_walksf[(size_t)seq*L_ + t + 1];
    int o = threadIdx.x;   // 64
    float v = y0[(size_t)node*OR_ + o];
    __shared__ float red[OR_];
    red[o] = v; __syncthreads();
    for (int st = OR_/2; st > 0; st >>= 1) {
        if (o < st) red[o] += red[o+st];
        __syncthreads();
    }
    if (o == 0) g_part1[b] = red[0];
}

__global__ void lred1_kernel()
{
    __shared__ float red[256];
    int tid = threadIdx.x;
    float s = 0.f;
    for (int i = tid; i < NB_LOSS; i += 256) s += g_part1[i];
    red[tid] = s; __syncthreads();
    for (int st = 128; st > 0; st >>= 1) {
        if (tid < st) red[tid] += red[tid+st];
        __syncthreads();
    }
    if (tid == 0) g_posw = LOSS_CNT / red[0];
}

__global__ void lbce_kernel(const int* __restrict__ idxs, const float* __restrict__ y0,
                            const float* __restrict__ Wss, const float* __restrict__ bss)
{
    int b = blockIdx.x;
    int t = b % (L_-1), j = (b/(L_-1)) % SUB_, s = b/((L_-1)*SUB_);
    int seq = s*N_ + idxs[j];
    __shared__ float yrow[F_];
    int o = threadIdx.x;   // 64
    yrow[o]      = g_yseq[t][(size_t)seq*F_ + o];
    yrow[o + 64] = g_yseq[t][(size_t)seq*F_ + o + 64];
    __syncthreads();
    float acc = bss[o];
    const float4* wr = (const float4*)(Wss + (size_t)o*F_);
#pragma unroll 8
    for (int k = 0; k < F_/4; k++) {
        float4 w = wr[k];
        acc += yrow[k*4+0]*w.x + yrow[k*4+1]*w.y + yrow[k*4+2]*w.z + yrow[k*4+3]*w.w;
    }
    int node = g_walksf[(size_t)seq*L_ + t + 1];
    float yt = y0[(size_t)node*OR_ + o];
    float term = g_posw * yt * softplusf(-acc) + (1.f - yt) * softplusf(acc);
    __shared__ float red[OR_];
    red[o] = term; __syncthreads();
    for (int st = OR_/2; st > 0; st >>= 1) {
        if (o < st) red[o] += red[o+st];
        __syncthreads();
    }
    if (o == 0) g_part2[b] = red[0];
}

__global__ void lred2_kernel(float* __restrict__ dst)
{
    __shared__ float red[256];
    int tid = threadIdx.x;
    float s = 0.f;
    for (int i = tid; i < NB_LOSS; i += 256) s += g_part2[i];
    red[tid] = s; __syncthreads();
    for (int st = 128; st > 0; st >>= 1) {
        if (tid < st) red[tid] += red[tid+st];
        __syncthreads();
    }
    if (tid == 0) *dst = red[0] / LOSS_CNT;
}

// ---------------- launch ----------------
extern "C" void kernel_launch(void* const* d_in, const int* in_sizes, int n_in,
                              void* d_out, int out_size)
{
    const float* h     = (const float*)d_in[0];
    const float* y0    = (const float*)d_in[1];
    const float* Wih_w = (const float*)d_in[2];
    const float* Whh_w = (const float*)d_in[3];
    const float* bih_w = (const float*)d_in[4];
    const float* bhh_w = (const float*)d_in[5];
    const float* Wih   = (const float*)d_in[6];
    const float* Whh   = (const float*)d_in[7];
    const float* bih   = (const float*)d_in[8];
    const float* bhh   = (const float*)d_in[9];
    const float* W_ss  = (const float*)d_in[10];
    const float* b_ss  = (const float*)d_in[11];
    const int*   walks = (const int*)d_in[12];
    const int*   idxs  = (const int*)d_in[13];
    float* out = (float*)d_out;

    const int SMEM_GRU = (MB_*132*2 + 32*128) * 4 + MB_ * 4;   // 84224 B
    const int SMEM_P   = (MB_*132 + 32*128) * 4;               // 50176 B
    cudaFuncSetAttribute(gru_kernel<0>, cudaFuncAttributeMaxDynamicSharedMemorySize, SMEM_GRU);
    cudaFuncSetAttribute(gru_kernel<1>, cudaFuncAttributeMaxDynamicSharedMemorySize, SMEM_GRU);
    cudaFuncSetAttribute(p_kernel,      cudaFuncAttributeMaxDynamicSharedMemorySize, SMEM_P);

    prep_kernel<<<(SEQ_ + 255)/256, 256>>>(walks);
    wg_kernel<<<1, G3_>>>(Wih_w, bih_w);
    p_kernel<<<(N_ + MB_-1)/MB_, NT_, SMEM_P>>>(h, Wih, bih);
    gru_kernel<0><<<SEQ_/MB_, NT_, SMEM_GRU>>>(Whh_w, bhh_w, nullptr, nullptr);
    gru_kernel<1><<<SEQ_/MB_, NT_, SMEM_GRU>>>(Whh, bhh, Wih, out);
    lsum_kernel<<<NB_LOSS, OR_>>>(idxs, y0);
    lred1_kernel<<<1, 256>>>();
    lbce_kernel<<<NB_LOSS, OR_>>>(idxs, y0, W_ss, b_ss);
    lred2_kernel<<<1, 256>>>(out + (out_size - 1));
}

// round 3
// speedup vs baseline: 3.1748x; 3.1703x over previous
#include <cuda_runtime.h>
#include <cuda_bf16.h>
#include <math.h>
#include <stdint.h>

#define S_    4
#define N_    10000
#define L_    8
#define F_    128
#define G3_   384
#define OR_   64
#define SUB_  100
#define SEQ_  (S_*N_)
#define MB_   64
#define NT_   256
#define NB_LOSS (S_*SUB_*(L_-1))
#define LOSS_CNT 179200.0f
#define APITCH 264
#define BPITCH 136
#define CHUNKE (128*BPITCH)

__device__ int      g_walksf[SEQ_*L_];
__device__ unsigned g_upk[SEQ_];
__device__ float    g_wg[8*G3_];
__device__ float    g_P[N_*G3_];
__device__ __nv_bfloat16 g_yw2[(size_t)L_*SEQ_*256];   // GRU1 out, split (hi|lo)
__device__ float    g_yseq[L_-1][SEQ_*F_];
__device__ float    g_part1[NB_LOSS];
__device__ float    g_part2[NB_LOSS];
__device__ float    g_posw;
__device__ __nv_bfloat16 g_W1h[G3_*F_], g_W1l[G3_*F_];  // Whh_w split
__device__ __nv_bfloat16 g_W2h[G3_*F_], g_W2l[G3_*F_];  // Whh split
__device__ __nv_bfloat16 g_WXh[G3_*F_], g_WXl[G3_*F_];  // Wih[:,128:256] split

__device__ __forceinline__ float sigf(float x) { return __fdividef(1.f, 1.f + __expf(-x)); }
__device__ __forceinline__ float tanh_s(float x) {
    float ax = fabsf(x); float e = __expf(-2.f*ax);
    return copysignf(__fdividef(1.f - e, 1.f + e), x);
}
__device__ __forceinline__ float softplusf(float x) {
    return fmaxf(x, 0.f) + log1pf(__expf(-fabsf(x)));
}
__device__ __forceinline__ float2 unpackbf(uint32_t u) {
    __nv_bfloat162 v = *(__nv_bfloat162*)&u;
    return make_float2(__bfloat162float(v.x), __bfloat162float(v.y));
}
__device__ __forceinline__ uint32_t packbf(float a, float b) {
    __nv_bfloat162 v = __floats2bfloat162_rn(a, b);
    return *(uint32_t*)&v;
}

__device__ __forceinline__ void mma16816(float c[4], uint32_t a0, uint32_t a1,
                                         uint32_t a2, uint32_t a3, uint32_t b0, uint32_t b1) {
    asm volatile("mma.sync.aligned.m16n8k16.row.col.f32.bf16.bf16.f32 "
                 "{%0,%1,%2,%3}, {%4,%5,%6,%7}, {%8,%9}, {%0,%1,%2,%3};\n"
                 : "+f"(c[0]), "+f"(c[1]), "+f"(c[2]), "+f"(c[3])
                 : "r"(a0), "r"(a1), "r"(a2), "r"(a3), "r"(b0), "r"(b1));
}

// acc[2][4][4] += A(32 rows x 256 split) @ W^T (hi chunk at B, lo at B+CHUNKE)
__device__ __forceinline__ void run_gemm(float (&acc)[2][4][4],
    const __nv_bfloat16* __restrict__ A,   // warp row base applied
    const __nv_bfloat16* __restrict__ B,
    int g, int tg2, int wc)
{
#pragma unroll
    for (int seg = 0; seg < 3; seg++) {
        const __nv_bfloat16* Ax = A + ((seg == 1) ? 128 : 0);
        const __nv_bfloat16* Bx = B + ((seg == 2) ? CHUNKE : 0);
#pragma unroll
        for (int ks = 0; ks < 8; ks++) {
            const int k0 = ks*16 + tg2;
            uint32_t a[2][4];
#pragma unroll
            for (int mt = 0; mt < 2; mt++) {
                const __nv_bfloat16* Ar = Ax + (mt*16 + g)*APITCH + k0;
                a[mt][0] = *(const uint32_t*)Ar;
                a[mt][1] = *(const uint32_t*)(Ar + 8*APITCH);
                a[mt][2] = *(const uint32_t*)(Ar + 8);
                a[mt][3] = *(const uint32_t*)(Ar + 8*APITCH + 8);
            }
#pragma unroll
            for (int nt = 0; nt < 4; nt++) {
                const __nv_bfloat16* Br = Bx + (wc*32 + nt*8 + g)*BPITCH + k0;
                uint32_t b0 = *(const uint32_t*)Br;
                uint32_t b1 = *(const uint32_t*)(Br + 8);
                mma16816(acc[0][nt], a[0][0], a[0][1], a[0][2], a[0][3], b0, b1);
                mma16816(acc[1][nt], a[1][0], a[1][1], a[1][2], a[1][3], b0, b1);
            }
        }
    }
}

// stage one gate's (hi,lo) 128x128 pair into smem chunk pair
__device__ __forceinline__ void stage_pair(__nv_bfloat16* dst,
    const __nv_bfloat16* __restrict__ hi, const __nv_bfloat16* __restrict__ lo,
    int jg, int tid)
{
    const __nv_bfloat16* s0 = hi + (size_t)jg*128*128;
    const __nv_bfloat16* s1 = lo + (size_t)jg*128*128;
#pragma unroll
    for (int it = 0; it < 8; it++) {
        int i = tid + it*NT_;
        int row = i >> 4, seg = (i & 15) << 3;
        *(uint4*)(dst + row*BPITCH + seg)          = *(const uint4*)(s0 + row*128 + seg);
        *(uint4*)(dst + CHUNKE + row*BPITCH + seg) = *(const uint4*)(s1 + row*128 + seg);
    }
}

// ---------------- preprocessing ----------------
__global__ void prep_kernel(const int* __restrict__ walks)
{
    int m = blockIdx.x * blockDim.x + threadIdx.x;
    if (m >= SEQ_) return;
    int w[L_];
#pragma unroll
    for (int p = 0; p < L_; p++) w[p] = walks[m*L_ + p];
    unsigned pk = 0;
#pragma unroll
    for (int t = 0; t < L_; t++) {
        int p = L_-1-t, wp = w[p], u = p;
#pragma unroll
        for (int q = L_-1; q >= 0; q--) if (w[q] == wp) u = q;
        g_walksf[m*L_ + t] = wp;
        pk |= ((unsigned)u) << (4*t);
    }
    g_upk[m] = pk;
}

__global__ void wg_kernel(const float* __restrict__ Wih_w, const float* __restrict__ bih_w)
{
    int j = threadIdx.x;
    float b = bih_w[j];
#pragma unroll
    for (int u = 0; u < 8; u++) g_wg[u*G3_ + j] = Wih_w[j*8 + u] + b;
}

__global__ void pack_kernel(const float* __restrict__ Whh_w, const float* __restrict__ Whh,
                            const float* __restrict__ Wih)
{
    int i = blockIdx.x * 256 + threadIdx.x;
    if (i >= G3_*F_) return;
    float a = Whh_w[i];
    __nv_bfloat16 h1 = __float2bfloat16(a);
    g_W1h[i] = h1; g_W1l[i] = __float2bfloat16(a - __bfloat162float(h1));
    float b = Whh[i];
    __nv_bfloat16 h2 = __float2bfloat16(b);
    g_W2h[i] = h2; g_W2l[i] = __float2bfloat16(b - __bfloat162float(h2));
    int n = i >> 7, k = i & 127;
    float c = Wih[n*256 + 128 + k];
    __nv_bfloat16 h3 = __float2bfloat16(c);
    g_WXh[i] = h3; g_WXl[i] = __float2bfloat16(c - __bfloat162float(h3));
}

// ---------------- P = h @ WihA^T + bih (fp32 scalar, small) ----------------
__device__ __forceinline__ void gemm_tile(float acc[4][8], const float* __restrict__ sh_src,
    float* __restrict__ sh_w, const float* __restrict__ W, int wstride, int tx, int ty, int tid)
{
    for (int k0 = 0; k0 < F_; k0 += 32) {
        __syncthreads();
        {
            int j = tid >> 1, half = tid & 1;
            const float* src = W + (size_t)j*wstride + k0 + half*16;
#pragma unroll
            for (int q = 0; q < 4; q++) {
                float4 v = *(const float4*)(src + q*4);
                int kk = half*16 + q*4;
                sh_w[(kk+0)*128+j]=v.x; sh_w[(kk+1)*128+j]=v.y;
                sh_w[(kk+2)*128+j]=v.z; sh_w[(kk+3)*128+j]=v.w;
            }
        }
        __syncthreads();
        const float* s0 = sh_src + (ty*4+0)*132 + k0;
        const float* s1 = sh_src + (ty*4+1)*132 + k0;
        const float* s2 = sh_src + (ty*4+2)*132 + k0;
        const float* s3 = sh_src + (ty*4+3)*132 + k0;
#pragma unroll 8
        for (int kk = 0; kk < 32; kk++) {
            float4 wa = *(const float4*)&sh_w[kk*128 + tx*8];
            float4 wb = *(const float4*)&sh_w[kk*128 + tx*8 + 4];
            float h0=s0[kk], h1=s1[kk], h2=s2[kk], h3=s3[kk];
            acc[0][0]+=h0*wa.x; acc[0][1]+=h0*wa.y; acc[0][2]+=h0*wa.z; acc[0][3]+=h0*wa.w;
            acc[0][4]+=h0*wb.x; acc[0][5]+=h0*wb.y; acc[0][6]+=h0*wb.z; acc[0][7]+=h0*wb.w;
            acc[1][0]+=h1*wa.x; acc[1][1]+=h1*wa.y; acc[1][2]+=h1*wa.z; acc[1][3]+=h1*wa.w;
            acc[1][4]+=h1*wb.x; acc[1][5]+=h1*wb.y; acc[1][6]+=h1*wb.z; acc[1][7]+=h1*wb.w;
            acc[2][0]+=h2*wa.x; acc[2][1]+=h2*wa.y; acc[2][2]+=h2*wa.z; acc[2][3]+=h2*wa.w;
            acc[2][4]+=h2*wb.x; acc[2][5]+=h2*wb.y; acc[2][6]+=h2*wb.z; acc[2][7]+=h2*wb.w;
            acc[3][0]+=h3*wa.x; acc[3][1]+=h3*wa.y; acc[3][2]+=h3*wa.z; acc[3][3]+=h3*wa.w;
            acc[3][4]+=h3*wb.x; acc[3][5]+=h3*wb.y; acc[3][6]+=h3*wb.z; acc[3][7]+=h3*wb.w;
        }
    }
}

__global__ void __launch_bounds__(NT_) p_kernel(const float* __restrict__ h,
                                                const float* __restrict__ Wih,
                                                const float* __restrict__ bih)
{
    extern __shared__ float sm[];
    float* sh_s = sm;
    float* sh_w = sh_s + MB_*132;
    int tid = threadIdx.x, tx = tid & 15, ty = tid >> 4;
    int r0 = blockIdx.x * MB_;
    for (int i = tid; i < MB_*F_; i += NT_) {
        int r = i >> 7, k = i & 127, n = r0 + r;
        sh_s[r*132 + k] = (n < N_) ? h[(size_t)n*F_ + k] : 0.f;
    }
    __syncthreads();
    for (int jg = 0; jg < 3; jg++) {
        int jbase = jg*F_ + tx*8;
        float acc[4][8];
        {
            const float4* bp = (const float4*)(bih + jbase);
            float4 a = bp[0], b = bp[1];
            float bb[8] = {a.x,a.y,a.z,a.w,b.x,b.y,b.z,b.w};
#pragma unroll
            for (int mm = 0; mm < 4; mm++)
#pragma unroll
                for (int jj = 0; jj < 8; jj++) acc[mm][jj] = bb[jj];
        }
        gemm_tile(acc, sh_s, sh_w, Wih + (size_t)jg*F_*256, 256, tx, ty, tid);
#pragma unroll
        for (int mm = 0; mm < 4; mm++) {
            int n = r0 + ty*4 + mm;
            if (n < N_) {
                *(float4*)(g_P + (size_t)n*G3_ + jbase)   = make_float4(acc[mm][0],acc[mm][1],acc[mm][2],acc[mm][3]);
                *(float4*)(g_P + (size_t)n*G3_ + jbase+4) = make_float4(acc[mm][4],acc[mm][5],acc[mm][6],acc[mm][7]);
            }
        }
    }
}

// ---------------- fused tensor-core GRU ----------------
template<int IS2>
__global__ void __launch_bounds__(NT_, 1) gruT_kernel(const float* __restrict__ bhh,
                                                      float* __restrict__ hT_out)
{
    extern __shared__ char smc[];
    __nv_bfloat16* sh_h2 = (__nv_bfloat16*)smc;                       // 64 x APITCH
    __nv_bfloat16* sh_x2 = (__nv_bfloat16*)(smc + 33792);             // IS2 only
    float*         sh_wg = (float*)(smc + 33792);                     // GRU1 only (8x384)
    __nv_bfloat16* sh_B  = (__nv_bfloat16*)(smc + (IS2 ? 67584 : 46080));
    float*         sh_bh = (float*)(smc + (IS2 ? 206848 : 115712));
    int*           sh_i  = (int*)(sh_bh + G3_);

    const int tid = threadIdx.x, wid = tid >> 5, lane = tid & 31;
    const int wr = wid & 1, wc = wid >> 1;           // 2 row-warps x 4 col-warps
    const int g = lane >> 2, tg2 = (lane & 3)*2;
    const int rbase = wr*32;
    const int m0 = blockIdx.x * MB_;

    const __nv_bfloat16* WHi = IS2 ? g_W2h : g_W1h;
    const __nv_bfloat16* WHl = IS2 ? g_W2l : g_W1l;
    __nv_bfloat16* sh_BH = sh_B + (IS2 ? 2*CHUNKE : 0);   // h-weight chunk pair

    for (int i = tid; i < G3_; i += NT_) sh_bh[i] = bhh[i];
    if constexpr (IS2) {
#pragma unroll
        for (int it = 0; it < 8; it++) {
            int i = tid + it*NT_;
            int row = i >> 5, seg = (i & 31) << 3;
            *(uint4*)(sh_h2 + row*APITCH + seg) =
                *(const uint4*)(g_yw2 + ((size_t)(L_-1)*SEQ_ + m0 + row)*256 + seg);
        }
    } else {
        for (int i = tid; i < 64*APITCH/2; i += NT_) ((uint32_t*)sh_h2)[i] = 0u;
        for (int i = tid; i < 8*G3_; i += NT_) sh_wg[i] = g_wg[i];
        if (tid < MB_) sh_i[tid] = (int)g_upk[m0 + tid];
    }

    float rr[2][4][4], zz[2][4][4];

#pragma unroll 1
    for (int t = 0; t < L_; t++) {
        if constexpr (IS2) {
#pragma unroll
            for (int it = 0; it < 8; it++) {
                int i = tid + it*NT_;
                int row = i >> 5, seg = (i & 31) << 3;
                *(uint4*)(sh_x2 + row*APITCH + seg) =
                    *(const uint4*)(g_yw2 + ((size_t)t*SEQ_ + m0 + row)*256 + seg);
            }
            if (tid < MB_) sh_i[tid] = g_walksf[(size_t)(m0 + tid)*L_ + t];
        }

#pragma unroll 1
        for (int jg = 0; jg < 3; jg++) {
            __syncthreads();
            if constexpr (IS2) stage_pair(sh_B, g_WXh, g_WXl, jg, tid);
            stage_pair(sh_BH, WHi, WHl, jg, tid);
            __syncthreads();

            float acci[2][4][4], acch[2][4][4];
#pragma unroll
            for (int mt = 0; mt < 2; mt++) {
                int rl = rbase + mt*16 + g;
                int i0, i1;
                if constexpr (IS2) { i0 = sh_i[rl]; i1 = sh_i[rl+8]; }
                else {
                    i0 = (sh_i[rl]   >> (4*t)) & 7;
                    i1 = (sh_i[rl+8] >> (4*t)) & 7;
                }
#pragma unroll
                for (int nt = 0; nt < 4; nt++) {
                    int cc = jg*F_ + wc*32 + nt*8 + tg2;
                    float2 bh = *(const float2*)&sh_bh[cc];
                    float2 p0, p1;
                    if constexpr (IS2) {
                        p0 = *(const float2*)&g_P[(size_t)i0*G3_ + cc];
                        p1 = *(const float2*)&g_P[(size_t)i1*G3_ + cc];
                    } else {
                        p0 = *(const float2*)&sh_wg[i0*G3_ + cc];
                        p1 = *(const float2*)&sh_wg[i1*G3_ + cc];
                    }
                    acci[mt][nt][0]=p0.x; acci[mt][nt][1]=p0.y;
                    acci[mt][nt][2]=p1.x; acci[mt][nt][3]=p1.y;
                    acch[mt][nt][0]=bh.x; acch[mt][nt][1]=bh.y;
                    acch[mt][nt][2]=bh.x; acch[mt][nt][3]=bh.y;
                }
            }
            if constexpr (IS2) run_gemm(acci, sh_x2 + rbase*APITCH, sh_B, g, tg2, wc);
            run_gemm(acch, sh_h2 + rbase*APITCH, sh_BH, g, tg2, wc);

            if (jg == 0) {
#pragma unroll
                for (int mt=0; mt<2; mt++)
#pragma unroll
                    for (int nt=0; nt<4; nt++)
#pragma unroll
                        for (int q=0; q<4; q++)
                            rr[mt][nt][q] = sigf(acci[mt][nt][q] + acch[mt][nt][q]);
            } else if (jg == 1) {
#pragma unroll
                for (int mt=0; mt<2; mt++)
#pragma unroll
                    for (int nt=0; nt<4; nt++)
#pragma unroll
                        for (int q=0; q<4; q++)
                            zz[mt][nt][q] = sigf(acci[mt][nt][q] + acch[mt][nt][q]);
            } else {
                __syncthreads();   // all warps done reading sh_h2
#pragma unroll
                for (int mt=0; mt<2; mt++)
#pragma unroll
                    for (int nt=0; nt<4; nt++) {
                        int cc = wc*32 + nt*8 + tg2;
#pragma unroll
                        for (int p2=0; p2<2; p2++) {
                            int r = rbase + mt*16 + g + p2*8;
                            float n0 = tanh_s(acci[mt][nt][p2*2]   + rr[mt][nt][p2*2]  *acch[mt][nt][p2*2]);
                            float n1 = tanh_s(acci[mt][nt][p2*2+1] + rr[mt][nt][p2*2+1]*acch[mt][nt][p2*2+1]);
                            float z0 = zz[mt][nt][p2*2], z1 = zz[mt][nt][p2*2+1];
                            float2 hh = unpackbf(*(uint32_t*)&sh_h2[r*APITCH + cc]);
                            float2 hl = unpackbf(*(uint32_t*)&sh_h2[r*APITCH + 128 + cc]);
                            float h0 = (1.f - z0)*n0 + z0*(hh.x + hl.x);
                            float h1 = (1.f - z1)*n1 + z1*(hh.y + hl.y);
                            __nv_bfloat16 s0 = __float2bfloat16(h0), s1 = __float2bfloat16(h1);
                            uint32_t hiv = packbf(__bfloat162float(s0), __bfloat162float(s1));
                            // exact hi pack:
                            { __nv_bfloat162 hv; hv.x = s0; hv.y = s1; hiv = *(uint32_t*)&hv; }
                            uint32_t lov = packbf(h0 - __bfloat162float(s0), h1 - __bfloat162float(s1));
                            *(uint32_t*)&sh_h2[r*APITCH + cc] = hiv;
                            *(uint32_t*)&sh_h2[r*APITCH + 128 + cc] = lov;
                            if constexpr (IS2) {
                                float* dst = (t < L_-1) ? (g_yseq[t] + ((size_t)(m0+r))*F_ + cc)
                                                        : (hT_out   + ((size_t)(m0+r))*F_ + cc);
                                *(float2*)dst = make_float2(h0, h1);
                            } else {
                                size_t base = ((size_t)t*SEQ_ + m0 + r)*256 + cc;
                                *(uint32_t*)&g_yw2[base]       = hiv;
                                *(uint32_t*)&g_yw2[base + 128] = lov;
                            }
                        }
                    }
            }
        }
    }
}

// ---------------- loss ----------------
__global__ void lsum_kernel(const int* __restrict__ idxs, const float* __restrict__ y0)
{
    int b = blockIdx.x;
    int t = b % (L_-1), j = (b/(L_-1)) % SUB_, s = b/((L_-1)*SUB_);
    int seq = s*N_ + idxs[j];
    int node = g_walksf[(size_t)seq*L_ + t + 1];
    int o = threadIdx.x;
    __shared__ float red[OR_];
    red[o] = y0[(size_t)node*OR_ + o]; __syncthreads();
    for (int st = OR_/2; st > 0; st >>= 1) { if (o < st) red[o] += red[o+st]; __syncthreads(); }
    if (o == 0) g_part1[b] = red[0];
}

__global__ void lred1_kernel()
{
    __shared__ float red[256];
    int tid = threadIdx.x; float s = 0.f;
    for (int i = tid; i < NB_LOSS; i += 256) s += g_part1[i];
    red[tid] = s; __syncthreads();
    for (int st = 128; st > 0; st >>= 1) { if (tid < st) red[tid] += red[tid+st]; __syncthreads(); }
    if (tid == 0) g_posw = LOSS_CNT / red[0];
}

__global__ void lbce_kernel(const int* __restrict__ idxs, const float* __restrict__ y0,
                            const float* __restrict__ Wss, const float* __restrict__ bss)
{
    int b = blockIdx.x;
    int t = b % (L_-1), j = (b/(L_-1)) % SUB_, s = b/((L_-1)*SUB_);
    int seq = s*N_ + idxs[j];
    __shared__ float yrow[F_];
    int o = threadIdx.x;
    yrow[o]      = g_yseq[t][(size_t)seq*F_ + o];
    yrow[o + 64] = g_yseq[t][(size_t)seq*F_ + o + 64];
    __syncthreads();
    float acc = bss[o];
    const float4* wrp = (const float4*)(Wss + (size_t)o*F_);
#pragma unroll 8
    for (int k = 0; k < F_/4; k++) {
        float4 w = wrp[k];
        acc += yrow[k*4]*w.x + yrow[k*4+1]*w.y + yrow[k*4+2]*w.z + yrow[k*4+3]*w.w;
    }
    int node = g_walksf[(size_t)seq*L_ + t + 1];
    float yt = y0[(size_t)node*OR_ + o];
    float term = g_posw * yt * softplusf(-acc) + (1.f - yt) * softplusf(acc);
    __shared__ float red[OR_];
    red[o] = term; __syncthreads();
    for (int st = OR_/2; st > 0; st >>= 1) { if (o < st) red[o] += red[o+st]; __syncthreads(); }
    if (o == 0) g_part2[b] = red[0];
}

__global__ void lred2_kernel(float* __restrict__ dst)
{
    __shared__ float red[256];
    int tid = threadIdx.x; float s = 0.f;
    for (int i = tid; i < NB_LOSS; i += 256) s += g_part2[i];
    red[tid] = s; __syncthreads();
    for (int st = 128; st > 0; st >>= 1) { if (tid < st) red[tid] += red[tid+st]; __syncthreads(); }
    if (tid == 0) *dst = red[0] / LOSS_CNT;
}

// ---------------- launch ----------------
extern "C" void kernel_launch(void* const* d_in, const int* in_sizes, int n_in,
                              void* d_out, int out_size)
{
    const float* h     = (const float*)d_in[0];
    const float* y0    = (const float*)d_in[1];
    const float* Wih_w = (const float*)d_in[2];
    const float* Whh_w = (const float*)d_in[3];
    const float* bih_w = (const float*)d_in[4];
    const float* bhh_w = (const float*)d_in[5];
    const float* Wih   = (const float*)d_in[6];
    const float* Whh   = (const float*)d_in[7];
    const float* bih   = (const float*)d_in[8];
    const float* bhh   = (const float*)d_in[9];
    const float* W_ss  = (const float*)d_in[10];
    const float* b_ss  = (const float*)d_in[11];
    const int*   walks = (const int*)d_in[12];
    const int*   idxs  = (const int*)d_in[13];
    float* out = (float*)d_out;

    const int SMEM_P  = (MB_*132 + 32*128) * 4;        // 50176
    const int SMEM_G1 = 115712 + G3_*4 + MB_*4;        // 117504
    const int SMEM_G2 = 206848 + G3_*4 + MB_*4;        // 208640
    cudaFuncSetAttribute(p_kernel,      cudaFuncAttributeMaxDynamicSharedMemorySize, SMEM_P);
    cudaFuncSetAttribute(gruT_kernel<0>, cudaFuncAttributeMaxDynamicSharedMemorySize, SMEM_G1);
    cudaFuncSetAttribute(gruT_kernel<1>, cudaFuncAttributeMaxDynamicSharedMemorySize, SMEM_G2);

    prep_kernel<<<(SEQ_ + 255)/256, 256>>>(walks);
    wg_kernel<<<1, G3_>>>(Wih_w, bih_w);
    pack_kernel<<<(G3_*F_ + 255)/256, 256>>>(Whh_w, Whh, Wih);
    p_kernel<<<(N_ + MB_-1)/MB_, NT_, SMEM_P>>>(h, Wih, bih);
    gruT_kernel<0><<<SEQ_/MB_, NT_, SMEM_G1>>>(bhh_w, nullptr);
    gruT_kernel<1><<<SEQ_/MB_, NT_, SMEM_G2>>>(bhh, out);
    lsum_kernel<<<NB_LOSS, OR_>>>(idxs, y0);
    lred1_kernel<<<1, 256>>>();
    lbce_kernel<<<NB_LOSS, OR_>>>(idxs, y0, W_ss, b_ss);
    lred2_kernel<<<1, 256>>>(out + (out_size - 1));
}